// round 2
// baseline (speedup 1.0000x reference)
#include <cuda_runtime.h>
#include <math.h>
#include <stdint.h>

#define NN 100000
#define EE 6400000
#define RR 90

// ---------------- static device scratch (allocation-free rule) ----------------
__device__ int    g_cnt[(size_t)NN * RR];      // per (dst, rel) edge counts (36 MB)
__device__ float  g_inv[EE];                   // per-edge 1/count (25.6 MB)
__device__ float4 g_x4[NN];                    // x padded to 4 (stride 4)
__device__ float4 g_h1[(size_t)NN * 2];        // agg1 -> h1, stride 8 (6 used + 2 pad)
__device__ float4 g_h2[NN];                    // agg2 -> h2, stride 4 (3 used + 1 pad)
__device__ float4 g_a3[(size_t)NN * 2];        // agg3 -> h3, stride 8
__device__ float  g_pool[8];

// ---------------- zero everything that gets accumulated into ----------------
__global__ void zero_all() {
    int idx = blockIdx.x * blockDim.x + threadIdx.x;
    int stride = gridDim.x * blockDim.x;
    int4* c = (int4*)g_cnt;
    const int n_cnt4 = (NN * RR) / 4;                 // 2,250,000
    for (int i = idx; i < n_cnt4; i += stride) c[i] = make_int4(0, 0, 0, 0);
    float4 z4 = make_float4(0.f, 0.f, 0.f, 0.f);
    for (int i = idx; i < NN * 2; i += stride) g_h1[i] = z4;
    for (int i = idx; i < NN;     i += stride) g_h2[i] = z4;
    for (int i = idx; i < NN * 2; i += stride) g_a3[i] = z4;
    if (idx < 8) g_pool[idx] = 0.f;
}

// ---------------- pad x [N,3] -> float4 ----------------
__global__ void pad_x(const float* __restrict__ x) {
    int i = blockIdx.x * blockDim.x + threadIdx.x;
    if (i < NN) {
        g_x4[i] = make_float4(x[i * 3 + 0], x[i * 3 + 1], x[i * 3 + 2], 0.f);
    }
}

// ---------------- count pass: cnt[dst*R + et] += 1 ----------------
__global__ void count_k(const int* __restrict__ dst, const int* __restrict__ et) {
    int stride = gridDim.x * blockDim.x;
    for (int e = blockIdx.x * blockDim.x + threadIdx.x; e < EE; e += stride) {
        atomicAdd(&g_cnt[dst[e] * RR + et[e]], 1);
    }
}

// ---------------- per-edge inverse count (coalesced reuse in layers 1 & 3) ----------------
__global__ void inv_k(const int* __restrict__ dst, const int* __restrict__ et) {
    int stride = gridDim.x * blockDim.x;
    for (int e = blockIdx.x * blockDim.x + threadIdx.x; e < EE; e += stride) {
        int c = g_cnt[dst[e] * RR + et[e]];   // >= 1 since this edge counted
        g_inv[e] = 1.0f / (float)c;
    }
}

// ---------------- mean-aggr edge pass (layers 1 and 3): in 3-dim, out 6-dim ----------------
// msg[b*2+o] = in[src][b] * W[r][b][0][o] * inv[e];  red into agg row (stride 8)
__global__ void edge_mean(const int* __restrict__ src, const int* __restrict__ dst,
                          const int* __restrict__ et,  const float* __restrict__ W,
                          int layer3) {
    __shared__ float sW[RR * 6];
    for (int i = threadIdx.x; i < RR * 6; i += blockDim.x) sW[i] = W[i];
    __syncthreads();
    const float4* xin = layer3 ? g_h2 : g_x4;
    float* agg = layer3 ? (float*)g_a3 : (float*)g_h1;
    int stride = gridDim.x * blockDim.x;
    for (int e = blockIdx.x * blockDim.x + threadIdx.x; e < EE; e += stride) {
        int s = src[e], d = dst[e], r = et[e];
        float iv = g_inv[e];
        float4 xv = xin[s];
        const float* w = sW + r * 6;
        float m0 = xv.x * w[0] * iv, m1 = xv.x * w[1] * iv;
        float m2 = xv.y * w[2] * iv, m3 = xv.y * w[3] * iv;
        float m4 = xv.z * w[4] * iv, m5 = xv.z * w[5] * iv;
        float* base = agg + (size_t)d * 8;
        asm volatile("red.global.add.v4.f32 [%0], {%1,%2,%3,%4};"
                     :: "l"(base), "f"(m0), "f"(m1), "f"(m2), "f"(m3) : "memory");
        asm volatile("red.global.add.v2.f32 [%0], {%1,%2};"
                     :: "l"(base + 4), "f"(m4), "f"(m5) : "memory");
    }
}

// ---------------- add-aggr edge pass (layer 2): in 6-dim, out 3-dim ----------------
// msg[b] = h1[src][2b]*W[r][b][0] + h1[src][2b+1]*W[r][b][1];  single red.v4 (pad lane = 0)
__global__ void edge_add(const int* __restrict__ src, const int* __restrict__ dst,
                         const int* __restrict__ et,  const float* __restrict__ W) {
    __shared__ float sW[RR * 6];
    for (int i = threadIdx.x; i < RR * 6; i += blockDim.x) sW[i] = W[i];
    __syncthreads();
    int stride = gridDim.x * blockDim.x;
    for (int e = blockIdx.x * blockDim.x + threadIdx.x; e < EE; e += stride) {
        int s = src[e], d = dst[e], r = et[e];
        float4 a = g_h1[(size_t)s * 2];
        float4 b = g_h1[(size_t)s * 2 + 1];
        const float* w = sW + r * 6;
        float m0 = a.x * w[0] + a.y * w[1];
        float m1 = a.z * w[2] + a.w * w[3];
        float m2 = b.x * w[4] + b.y * w[5];
        float* base = (float*)g_h2 + (size_t)d * 4;
        asm volatile("red.global.add.v4.f32 [%0], {%1,%2,%3,%4};"
                     :: "l"(base), "f"(m0), "f"(m1), "f"(m2), "f"(0.f) : "memory");
    }
}

// ---------------- node 1: h1 = relu(agg1 + x@root1 + b1)  (in-place, 6-wide) ----------------
__global__ void node1(const float* __restrict__ root1, const float* __restrict__ b1) {
    int i = blockIdx.x * blockDim.x + threadIdx.x;
    if (i >= NN) return;
    float4 xv = g_x4[i];
    float* row = (float*)&g_h1[(size_t)i * 2];
    float h[6];
#pragma unroll
    for (int j = 0; j < 6; j++) {
        float v = row[j] + xv.x * root1[j] + xv.y * root1[6 + j] + xv.z * root1[12 + j] + b1[j];
        h[j] = v > 0.f ? v : 0.f;
    }
#pragma unroll
    for (int j = 0; j < 6; j++) row[j] = h[j];
    row[6] = 0.f; row[7] = 0.f;
}

// ---------------- node 2: h2 = relu(agg2 + h1@root2 + b2)  (in-place, 3-wide) ----------------
__global__ void node2(const float* __restrict__ root2, const float* __restrict__ b2) {
    int i = blockIdx.x * blockDim.x + threadIdx.x;
    if (i >= NN) return;
    float4 a = g_h1[(size_t)i * 2];
    float4 b = g_h1[(size_t)i * 2 + 1];
    float hin[6] = {a.x, a.y, a.z, a.w, b.x, b.y};
    float* row = (float*)&g_h2[i];
    float h[3];
#pragma unroll
    for (int j = 0; j < 3; j++) {
        float v = row[j] + b2[j];
#pragma unroll
        for (int k = 0; k < 6; k++) v += hin[k] * root2[k * 3 + j];
        h[j] = v > 0.f ? v : 0.f;
    }
    g_h2[i] = make_float4(h[0], h[1], h[2], 0.f);
}

// ---------------- node 3 + mean pool fused ----------------
__global__ void node3_pool(const float* __restrict__ root3, const float* __restrict__ b3) {
    int i = blockIdx.x * blockDim.x + threadIdx.x;
    int tid = threadIdx.x;
    float v[6];
    if (i < NN) {
        float4 xv = g_h2[i];
        const float* row = (const float*)&g_a3[(size_t)i * 2];
#pragma unroll
        for (int j = 0; j < 6; j++) {
            float t = row[j] + xv.x * root3[j] + xv.y * root3[6 + j] + xv.z * root3[12 + j] + b3[j];
            v[j] = t > 0.f ? t : 0.f;
        }
    } else {
#pragma unroll
        for (int j = 0; j < 6; j++) v[j] = 0.f;
    }
    // warp reduce each component
#pragma unroll
    for (int j = 0; j < 6; j++) {
#pragma unroll
        for (int off = 16; off > 0; off >>= 1)
            v[j] += __shfl_down_sync(0xFFFFFFFFu, v[j], off);
    }
    __shared__ float sp[6];
    if (tid < 6) sp[tid] = 0.f;
    __syncthreads();
    if ((tid & 31) == 0) {
#pragma unroll
        for (int j = 0; j < 6; j++) atomicAdd(&sp[j], v[j]);
    }
    __syncthreads();
    if (tid < 6) atomicAdd(&g_pool[tid], sp[tid]);
}

// ---------------- finalize: pooled mean + log_softmax ----------------
__global__ void finalize(float* __restrict__ out) {
    float v[6];
#pragma unroll
    for (int j = 0; j < 6; j++) v[j] = g_pool[j] / (float)NN;
    float m = v[0];
#pragma unroll
    for (int j = 1; j < 6; j++) m = fmaxf(m, v[j]);
    float s = 0.f;
#pragma unroll
    for (int j = 0; j < 6; j++) s += expf(v[j] - m);
    float l = logf(s);
#pragma unroll
    for (int j = 0; j < 6; j++) out[j] = v[j] - m - l;
}

extern "C" void kernel_launch(void* const* d_in, const int* in_sizes, int n_in,
                              void* d_out, int out_size) {
    const float* x     = (const float*)d_in[0];
    const int*   ei    = (const int*)d_in[1];
    const int*   src   = ei;
    const int*   dst   = ei + EE;
    const int*   et    = (const int*)d_in[3];
    const float* W1    = (const float*)d_in[4];
    const float* root1 = (const float*)d_in[5];
    const float* b1    = (const float*)d_in[6];
    const float* W2    = (const float*)d_in[7];
    const float* root2 = (const float*)d_in[8];
    const float* b2    = (const float*)d_in[9];
    const float* W3    = (const float*)d_in[10];
    const float* root3 = (const float*)d_in[11];
    const float* b3    = (const float*)d_in[12];
    float* out = (float*)d_out;

    const int NB_NODE = (NN + 255) / 256;

    zero_all<<<4096, 256>>>();
    pad_x<<<NB_NODE, 256>>>(x);
    count_k<<<2048, 256>>>(dst, et);
    inv_k<<<2048, 256>>>(dst, et);

    edge_mean<<<2048, 256>>>(src, dst, et, W1, 0);
    node1<<<NB_NODE, 256>>>(root1, b1);

    edge_add<<<2048, 256>>>(src, dst, et, W2);
    node2<<<NB_NODE, 256>>>(root2, b2);

    edge_mean<<<2048, 256>>>(src, dst, et, W3, 1);
    node3_pool<<<NB_NODE, 256>>>(root3, b3);

    finalize<<<1, 1>>>(out);
}